// round 12
// baseline (speedup 1.0000x reference)
#include <cuda_runtime.h>
#include <math.h>
#include <stdint.h>

// ---------------------------------------------------------------------------
// Problem constants
// ---------------------------------------------------------------------------
#define BB 4
#define NSEQ 1024
#define DM 1024
#define NH 16
#define HD 64
#define TD 768
#define TL 77
#define TTOK (BB * NSEQ)   // 4096
#define TCTX (BB * TL)     // 308

// ---------------------------------------------------------------------------
// Scratch (static device globals; no allocation allowed)
// ---------------------------------------------------------------------------
__device__ float g_mod[BB * 6 * DM];
__device__ float g_h[TTOK * DM];
__device__ float g_qkv[TTOK * 3 * DM];
__device__ float g_attn[TTOK * DM];
__device__ float g_x1[TTOK * DM];
__device__ float g_x2[TTOK * DM];
__device__ float g_ctx[TCTX * DM];
__device__ float g_qb[TTOK * DM];
__device__ float g_kc[TCTX * DM];
__device__ float g_vc[TCTX * DM];
__device__ float g_hidden[TTOK * 4 * DM];

// Pre-converted (tf32-rounded) weights + text, one big segment buffer.
#define OFF_QKV  0u
#define OFF_PROJ (OFF_QKV  + 1024u * 3072u)
#define OFF_CTX  (OFF_PROJ + 1024u * 1024u)
#define OFF_Q    (OFF_CTX  + 768u * 1024u)
#define OFF_K    (OFF_Q    + 1024u * 1024u)
#define OFF_V    (OFF_K    + 1024u * 1024u)
#define OFF_OUT  (OFF_V    + 1024u * 1024u)
#define OFF_FC1  (OFF_OUT  + 1024u * 1024u)
#define OFF_FC2  (OFF_FC1  + 1024u * 4096u)
#define OFF_TEXT (OFF_FC2  + 4096u * 1024u)
#define WC_TOTAL (OFF_TEXT + (uint32_t)(BB * TL * TD))
__device__ uint32_t g_wc[WC_TOTAL];

// ---------------------------------------------------------------------------
// Helpers
// ---------------------------------------------------------------------------
__device__ __forceinline__ float gelu_tanh(float x) {
    float x3 = x * x * x;
    float t  = tanhf(0.7978845608028654f * (x + 0.044715f * x3));
    return 0.5f * x * (1.0f + t);
}

__device__ __forceinline__ uint32_t f2tf32(float f) {
    uint32_t u;
    asm("cvt.rna.tf32.f32 %0, %1;" : "=r"(u) : "f"(f));
    return u;
}
__device__ __forceinline__ float rnaf(float f) {
    return __uint_as_float(f2tf32(f));
}
__device__ __forceinline__ uint4 rna4(float4 v) {
    return make_uint4(f2tf32(v.x), f2tf32(v.y), f2tf32(v.z), f2tf32(v.w));
}

__device__ __forceinline__ void mma1688(float* c, const uint32_t* a, const uint32_t* b) {
    asm volatile(
        "mma.sync.aligned.m16n8k8.row.col.f32.tf32.tf32.f32 "
        "{%0,%1,%2,%3}, {%4,%5,%6,%7}, {%8,%9}, {%0,%1,%2,%3};"
        : "+f"(c[0]), "+f"(c[1]), "+f"(c[2]), "+f"(c[3])
        : "r"(a[0]), "r"(a[1]), "r"(a[2]), "r"(a[3]), "r"(b[0]), "r"(b[1]));
}

__device__ __forceinline__ void ldsm4(uint32_t* r, uint32_t saddr) {
    asm volatile(
        "ldmatrix.sync.aligned.m8n8.x4.shared.b16 {%0,%1,%2,%3}, [%4];"
        : "=r"(r[0]), "=r"(r[1]), "=r"(r[2]), "=r"(r[3]) : "r"(saddr));
}

__device__ __forceinline__ void cpa16(uint32_t dst, const void* src, int srcBytes) {
    asm volatile("cp.async.cg.shared.global [%0], [%1], 16, %2;"
                 :: "r"(dst), "l"(src), "r"(srcBytes));
}
__device__ __forceinline__ void cpa_commit() {
    asm volatile("cp.async.commit_group;");
}
template <int N> __device__ __forceinline__ void cpa_wait() {
    asm volatile("cp.async.wait_group %0;" :: "n"(N));
}

// ---------------------------------------------------------------------------
// Single merged tf32 pre-convert kernel: converts all 10 segments in ONE
// launch (also: puts the first GEMM at launch #4 and proj GEMM at #6 so the
// fixed ncu -s 5 -c 1 capture profiles a GEMM).
// ---------------------------------------------------------------------------
__global__ void __launch_bounds__(256) cvt_all_kernel(
    const float* __restrict__ qkv, const float* __restrict__ proj,
    const float* __restrict__ ctx, const float* __restrict__ q,
    const float* __restrict__ k,   const float* __restrict__ v,
    const float* __restrict__ outw,const float* __restrict__ fc1,
    const float* __restrict__ fc2, const float* __restrict__ text,
    uint32_t* __restrict__ dst)
{
    const uint32_t i4 = blockIdx.x * 256 + threadIdx.x;
    const uint32_t total4 = WC_TOTAL / 4;
    if (i4 >= total4) return;
    const uint32_t w = i4 * 4;
    const float* src; uint32_t off;
    if      (w < OFF_PROJ) { src = qkv;  off = OFF_QKV;  }
    else if (w < OFF_CTX)  { src = proj; off = OFF_PROJ; }
    else if (w < OFF_Q)    { src = ctx;  off = OFF_CTX;  }
    else if (w < OFF_K)    { src = q;    off = OFF_Q;    }
    else if (w < OFF_V)    { src = k;    off = OFF_K;    }
    else if (w < OFF_OUT)  { src = v;    off = OFF_V;    }
    else if (w < OFF_FC1)  { src = outw; off = OFF_OUT;  }
    else if (w < OFF_FC2)  { src = fc1;  off = OFF_FC1;  }
    else if (w < OFF_TEXT) { src = fc2;  off = OFF_FC2;  }
    else                   { src = text; off = OFF_TEXT; }
    float4 vv = *(const float4*)(src + (w - off));
    *(uint4*)(dst + w) = rna4(vv);
}

// Epilogue modes
#define EPI_BIAS      0
#define EPI_BIAS_GELU 1
#define EPI_BIAS_RES  2
#define EPI_NOBIAS    3

// ---------------------------------------------------------------------------
// TF32 tensor-core GEMM v6: C[M,N] = A[M,K] @ W[K,N] (+bias)(+gelu)(+res)
// BM=BN=128, BK=8, 128 threads = 4 warps, warp tile 64x64 (measured-best).
// 4-stage cp.async ring (3 stages of prefetch in flight, ~1200+ cyc cover),
// ONE __syncthreads per iteration:
//   [wait(stage i) -> sync -> compute(i) -> issue(i+3)]
// stage i+3's buffer == stage i-1's, whose readers finished before this
// iteration's sync -> race-free. Tail commits empty groups so wait_group<2>
// always completes the oldest stage. Zero cvts in mainloop.
// Smem: 4*(128*12 + 8*136)*4 = 41.98 KB.
// ---------------------------------------------------------------------------
#define AS_PITCH 12
#define BS_PITCH 136
#define AS_BUFB (128 * AS_PITCH * 4)   // 6144 B per A stage
#define BS_BUFB (8 * BS_PITCH * 4)     // 4352 B per B stage

template <int EPI, bool ROUND>
__global__ void __launch_bounds__(128) tgemm_kernel(
    const float* __restrict__ A, const uint32_t* __restrict__ W,
    const float* __restrict__ bias, const float* __restrict__ res,
    float* __restrict__ C, int M, int N, int K)
{
    __shared__ uint32_t As[4][128][AS_PITCH];
    __shared__ uint32_t Bs[4][8][BS_PITCH];

    const int tid  = threadIdx.x;
    const int lane = tid & 31;
    const int warp = tid >> 5;
    const int g = lane >> 2;
    const int t = lane & 3;
    const int wm = (warp & 1) * 64;
    const int wn = (warp >> 1) * 64;
    const int rowBase = blockIdx.y * 128;
    const int colBase = blockIdx.x * 128;

    const uint32_t asBase = (uint32_t)__cvta_generic_to_shared(&As[0][0][0]);
    const uint32_t bsBase = (uint32_t)__cvta_generic_to_shared(&Bs[0][0][0]);

    // ldmatrix A-fragment addresses (pitch 12: banks 12r mod 32 all-distinct)
    const int j8  = lane & 7;
    const int mtx = lane >> 3;
    uint32_t aAddr[4];
#pragma unroll
    for (int mt = 0; mt < 4; mt++)
        aAddr[mt] = asBase +
            ((wm + mt * 16 + (mtx & 1) * 8 + j8) * AS_PITCH + (mtx >> 1) * 4) * 4;

    float acc[4][8][4];
#pragma unroll
    for (int mt = 0; mt < 4; mt++)
#pragma unroll
        for (int nt = 0; nt < 8; nt++)
#pragma unroll
            for (int i = 0; i < 4; i++) acc[mt][nt][i] = 0.0f;

    // stage loader: per stage A = 256 f4 (128 rows x 2), B = 256 f4 (8 k x 32)
    auto issueStage = [&](int stage, int k0) {
#pragma unroll
        for (int i = 0; i < 2; i++) {
            const int f4 = tid + i * 128;
            const int ar = f4 >> 1, ac = (f4 & 1) * 4;
            const int row = rowBase + ar;
            const int rowC = (row < M) ? row : 0;
            cpa16(asBase + (uint32_t)stage * AS_BUFB + (ar * AS_PITCH + ac) * 4,
                  A + (size_t)rowC * K + k0 + ac, (row < M) ? 16 : 0);
            const int bk = f4 >> 5, bn = (f4 & 31) * 4;
            cpa16(bsBase + (uint32_t)stage * BS_BUFB + (bk * BS_PITCH + bn) * 4,
                  W + (size_t)(k0 + bk) * N + colBase + bn, 16);
        }
        cpa_commit();
    };

    const int nk = K >> 3;     // number of 8-k stages (>= 96 for all call sites)
    issueStage(0, 0);
    issueStage(1, 8);
    issueStage(2, 16);

    for (int it = 0; it < nk; it++) {
        cpa_wait<2>();          // oldest stage (it) landed
        __syncthreads();        // visible to all; prior readers of buf (it-1)%4 done

        const int stage = it & 3;
        const uint32_t aOff = (uint32_t)stage * AS_BUFB;
        const uint32_t* __restrict__ bsBuf = &Bs[stage][0][0];

        uint32_t af[4][4];
#pragma unroll
        for (int mt = 0; mt < 4; mt++)
            ldsm4(af[mt], aAddr[mt] + aOff);
        uint32_t bf[8][2];
#pragma unroll
        for (int nt = 0; nt < 8; nt++) {
            bf[nt][0] = bsBuf[t       * BS_PITCH + wn + nt * 8 + g];
            bf[nt][1] = bsBuf[(t + 4) * BS_PITCH + wn + nt * 8 + g];
        }
#pragma unroll
        for (int mt = 0; mt < 4; mt++)
#pragma unroll
            for (int nt = 0; nt < 8; nt++)
                mma1688(acc[mt][nt], af[mt], bf[nt]);

        if (it + 3 < nk) issueStage((it + 3) & 3, (it + 3) * 8);
        else             cpa_commit();   // empty group keeps wait<2> exact
    }

    // Epilogue
#pragma unroll
    for (int mt = 0; mt < 4; mt++) {
        const int row0 = rowBase + wm + mt * 16 + g;
        const int row1 = row0 + 8;
#pragma unroll
        for (int nt = 0; nt < 8; nt++) {
            const int col = colBase + wn + nt * 8 + t * 2;
            float b0 = 0.f, b1 = 0.f;
            if (EPI != EPI_NOBIAS) { b0 = bias[col]; b1 = bias[col + 1]; }
            float v0 = acc[mt][nt][0] + b0;
            float v1 = acc[mt][nt][1] + b1;
            float v2 = acc[mt][nt][2] + b0;
            float v3 = acc[mt][nt][3] + b1;
            if (EPI == EPI_BIAS_GELU) {
                v0 = gelu_tanh(v0); v1 = gelu_tanh(v1);
                v2 = gelu_tanh(v2); v3 = gelu_tanh(v3);
            }
            if (ROUND) {
                v0 = rnaf(v0); v1 = rnaf(v1); v2 = rnaf(v2); v3 = rnaf(v3);
            }
            if (row0 < M) {
                if (EPI == EPI_BIAS_RES) {
                    float2 r = *(const float2*)(res + (size_t)row0 * N + col);
                    v0 += r.x; v1 += r.y;
                }
                *(float2*)(C + (size_t)row0 * N + col) = make_float2(v0, v1);
            }
            if (row1 < M) {
                if (EPI == EPI_BIAS_RES) {
                    float2 r = *(const float2*)(res + (size_t)row1 * N + col);
                    v2 += r.x; v3 += r.y;
                }
                *(float2*)(C + (size_t)row1 * N + col) = make_float2(v2, v3);
            }
        }
    }
}

// ---------------------------------------------------------------------------
// adaLN modulation
// ---------------------------------------------------------------------------
__global__ void __launch_bounds__(256) mod_kernel(
    const float* __restrict__ c, const float* __restrict__ W,
    const float* __restrict__ bias)
{
    const int b = blockIdx.y;
    const int col = blockIdx.x * 256 + threadIdx.x;
    __shared__ float sc[DM];
    for (int i = threadIdx.x; i < DM; i += 256) {
        float v = c[b * DM + i];
        sc[i] = v / (1.0f + __expf(-v));
    }
    __syncthreads();
    float acc = 0.0f;
#pragma unroll 8
    for (int k = 0; k < DM; k++)
        acc = fmaf(sc[k], W[(size_t)k * (6 * DM) + col], acc);
    g_mod[b * 6 * DM + col] = acc + bias[col];
}

// ---------------------------------------------------------------------------
// LayerNorm + modulate (output rounded to tf32 — feeds GEMMs only)
// ---------------------------------------------------------------------------
__global__ void __launch_bounds__(256) lnmod_kernel(
    const float* __restrict__ x, int shOff, int scOff, float* __restrict__ out)
{
    const int row = blockIdx.x;
    const int b = row >> 10;
    const int tid = threadIdx.x;

    float4 v = ((const float4*)(x + (size_t)row * DM))[tid];
    float s  = v.x + v.y + v.z + v.w;
    float s2 = v.x * v.x + v.y * v.y + v.z * v.z + v.w * v.w;

    __shared__ float red[16];
#pragma unroll
    for (int off = 16; off > 0; off >>= 1) {
        s  += __shfl_xor_sync(0xffffffffu, s,  off);
        s2 += __shfl_xor_sync(0xffffffffu, s2, off);
    }
    const int warp = tid >> 5, lane = tid & 31;
    if (lane == 0) { red[warp] = s; red[warp + 8] = s2; }
    __syncthreads();
    if (tid == 0) {
        float ts = 0.f, ts2 = 0.f;
#pragma unroll
        for (int i = 0; i < 8; i++) { ts += red[i]; ts2 += red[i + 8]; }
        float mu  = ts * (1.0f / DM);
        float var = ts2 * (1.0f / DM) - mu * mu;
        red[0] = mu;
        red[1] = rsqrtf(var + 1e-6f);
    }
    __syncthreads();
    const float mu = red[0], rs = red[1];

    const float* modp = g_mod + b * 6 * DM;
    const int cc = tid * 4;
    float4 sh  = *(const float4*)(modp + shOff + cc);
    float4 scv = *(const float4*)(modp + scOff + cc);
    float4 o;
    o.x = rnaf((v.x - mu) * rs * (1.0f + scv.x) + sh.x);
    o.y = rnaf((v.y - mu) * rs * (1.0f + scv.y) + sh.y);
    o.z = rnaf((v.z - mu) * rs * (1.0f + scv.z) + sh.z);
    o.w = rnaf((v.w - mu) * rs * (1.0f + scv.w) + sh.w);
    ((float4*)(out + (size_t)row * DM))[tid] = o;
}

// ---------------------------------------------------------------------------
// Tensor-core flash self-attention v3 (unchanged — passing at 167us).
// ---------------------------------------------------------------------------
#define KS_PITCH 76
#define VS_PITCH 88

__global__ void __launch_bounds__(128) flash_attn_kernel()
{
    __shared__ uint32_t Ks[64][KS_PITCH];
    __shared__ uint32_t Vs[64][VS_PITCH];

    const int qt = blockIdx.x, h = blockIdx.y, b = blockIdx.z;
    const int tid  = threadIdx.x;
    const int lane = tid & 31;
    const int warp = tid >> 5;
    const int g = lane >> 2;
    const int t = lane & 3;
    const int rw = warp * 32;
    const int qbase = b * NSEQ + qt * 128;

    uint32_t qa[8][2][4];
#pragma unroll
    for (int mt = 0; mt < 2; mt++) {
        const float* q0 = g_qkv + (size_t)(qbase + rw + mt * 16 + g) * (3 * DM) + h * 64;
        const float* q1 = q0 + (size_t)8 * (3 * DM);
#pragma unroll
        for (int ks = 0; ks < 8; ks++) {
            qa[ks][mt][0] = __float_as_uint(q0[ks * 8 + t]     * 0.125f);
            qa[ks][mt][1] = __float_as_uint(q1[ks * 8 + t]     * 0.125f);
            qa[ks][mt][2] = __float_as_uint(q0[ks * 8 + t + 4] * 0.125f);
            qa[ks][mt][3] = __float_as_uint(q1[ks * 8 + t + 4] * 0.125f);
        }
    }

    float o[2][8][4];
#pragma unroll
    for (int mt = 0; mt < 2; mt++)
#pragma unroll
        for (int nt = 0; nt < 8; nt++)
#pragma unroll
            for (int i = 0; i < 4; i++) o[mt][nt][i] = 0.0f;
    float mrow[2][2] = {{-1e30f, -1e30f}, {-1e30f, -1e30f}};
    float lrow[2][2] = {{0.f, 0.f}, {0.f, 0.f}};

    const int j8  = lane & 7;
    const int mtx = lane >> 3;
    const uint32_t ksBase = (uint32_t)__cvta_generic_to_shared(&Ks[0][0]);
    uint32_t kAddr[2];
#pragma unroll
    for (int p = 0; p < 2; p++)
        kAddr[p] = ksBase +
            ((p * 16 + (mtx >> 1) * 8 + j8) * KS_PITCH + (mtx & 1) * 4) * 4;

    const int src0 = (lane & ~3) | (t >> 1);
    const int src2 = src0 + 2;
    const bool odd = (t & 1) != 0;

    for (int kt = 0; kt < 16; kt++) {
        __syncthreads();
#pragma unroll
        for (int i = 0; i < 8; i++) {
            const int f4 = tid + i * 128;
            const int rk = f4 >> 4, c4 = f4 & 15;
            const size_t krow = (size_t)(b * NSEQ + kt * 64 + rk) * (3 * DM);
            *(uint4*)&Ks[rk][c4 * 4] =
                *(const uint4*)(g_qkv + krow + DM     + h * 64 + c4 * 4);
            *(uint4*)&Vs[rk][c4 * 4] =
                *(const uint4*)(g_qkv + krow + 2 * DM + h * 64 + c4 * 4);
        }
        __syncthreads();

#pragma unroll
        for (int c = 0; c < 2; c++) {
            float s[2][4][4];
#pragma unroll
            for (int mt = 0; mt < 2; mt++)
#pragma unroll
                for (int nt = 0; nt < 4; nt++)
#pragma unroll
                    for (int i = 0; i < 4; i++) s[mt][nt][i] = 0.0f;

#pragma unroll
            for (int ks = 0; ks < 8; ks++) {
                uint32_t bq[2][4];
#pragma unroll
                for (int p = 0; p < 2; p++)
                    ldsm4(bq[p], kAddr[p] + c * (32 * KS_PITCH * 4) + ks * 32);
#pragma unroll
                for (int mt = 0; mt < 2; mt++) {
                    mma1688(s[mt][0], qa[ks][mt], &bq[0][0]);
                    mma1688(s[mt][1], qa[ks][mt], &bq[0][2]);
                    mma1688(s[mt][2], qa[ks][mt], &bq[1][0]);
                    mma1688(s[mt][3], qa[ks][mt], &bq[1][2]);
                }
            }

#pragma unroll
            for (int mt = 0; mt < 2; mt++) {
                float tmax0 = -1e30f, tmax1 = -1e30f;
#pragma unroll
                for (int nt = 0; nt < 4; nt++) {
                    tmax0 = fmaxf(tmax0, fmaxf(s[mt][nt][0], s[mt][nt][1]));
                    tmax1 = fmaxf(tmax1, fmaxf(s[mt][nt][2], s[mt][nt][3]));
                }
                tmax0 = fmaxf(tmax0, __shfl_xor_sync(0xffffffffu, tmax0, 1));
                tmax0 = fmaxf(tmax0, __shfl_xor_sync(0xffffffffu, tmax0, 2));
                tmax1 = fmaxf(tmax1, __shfl_xor_sync(0xffffffffu, tmax1, 1));
                tmax1 = fmaxf(tmax1, __shfl_xor_sync(0xffffffffu, tmax1, 2));

                const float mn0 = fmaxf(mrow[mt][0], tmax0);
                const float mn1 = fmaxf(mrow[mt][1], tmax1);
                const float corr0 = __expf(mrow[mt][0] - mn0);
                const float corr1 = __expf(mrow[mt][1] - mn1);

                float sum0 = 0.f, sum1 = 0.f;
#pragma unroll
                for (int nt = 0; nt < 4; nt++) {
                    s[mt][nt][0] = __expf(s[mt][nt][0] - mn0); sum0 += s[mt][nt][0];
                    s[mt][nt][1] = __expf(s[mt][nt][1] - mn0); sum0 += s[mt][nt][1];
                    s[mt][nt][2] = __expf(s[mt][nt][2] - mn1); sum1 += s[mt][nt][2];
                    s[mt][nt][3] = __expf(s[mt][nt][3] - mn1); sum1 += s[mt][nt][3];
                }
                sum0 += __shfl_xor_sync(0xffffffffu, sum0, 1);
                sum0 += __shfl_xor_sync(0xffffffffu, sum0, 2);
                sum1 += __shfl_xor_sync(0xffffffffu, sum1, 1);
                sum1 += __shfl_xor_sync(0xffffffffu, sum1, 2);

                lrow[mt][0] = lrow[mt][0] * corr0 + sum0;
                lrow[mt][1] = lrow[mt][1] * corr1 + sum1;
                mrow[mt][0] = mn0; mrow[mt][1] = mn1;
#pragma unroll
                for (int nt = 0; nt < 8; nt++) {
                    o[mt][nt][0] *= corr0; o[mt][nt][1] *= corr0;
                    o[mt][nt][2] *= corr1; o[mt][nt][3] *= corr1;
                }
            }

#pragma unroll
            for (int kv_ = 0; kv_ < 4; kv_++) {
                const int kk = c * 32 + kv_ * 8;
                uint32_t pa[2][4];
#pragma unroll
                for (int mt = 0; mt < 2; mt++) {
                    float v0 = __shfl_sync(0xffffffffu, s[mt][kv_][0], src0);
                    float v1 = __shfl_sync(0xffffffffu, s[mt][kv_][1], src0);
                    float v2 = __shfl_sync(0xffffffffu, s[mt][kv_][2], src0);
                    float v3 = __shfl_sync(0xffffffffu, s[mt][kv_][3], src0);
                    float w0 = __shfl_sync(0xffffffffu, s[mt][kv_][0], src2);
                    float w1 = __shfl_sync(0xffffffffu, s[mt][kv_][1], src2);
                    float w2 = __shfl_sync(0xffffffffu, s[mt][kv_][2], src2);
                    float w3 = __shfl_sync(0xffffffffu, s[mt][kv_][3], src2);
                    pa[mt][0] = __float_as_uint(odd ? v1 : v0);
                    pa[mt][1] = __float_as_uint(odd ? v3 : v2);
                    pa[mt][2] = __float_as_uint(odd ? w1 : w0);
                    pa[mt][3] = __float_as_uint(odd ? w3 : w2);
                }
#pragma unroll
                for (int nt = 0; nt < 8; nt++) {
                    uint32_t bv[2];
                    bv[0] = Vs[kk + t][nt * 8 + g];
                    bv[1] = Vs[kk + t + 4][nt * 8 + g];
                    mma1688(o[0][nt], pa[0], bv);
                    mma1688(o[1][nt], pa[1], bv);
                }
            }
        }
    }

#pragma unroll
    for (int mt = 0; mt < 2; mt++) {
        const float inv0 = 1.0f / lrow[mt][0];
        const float inv1 = 1.0f / lrow[mt][1];
        float* op0 = g_attn + (size_t)(qbase + rw + mt * 16 + g) * DM + h * 64;
        float* op1 = op0 + (size_t)8 * DM;
#pragma unroll
        for (int nt = 0; nt < 8; nt++) {
            *(float2*)(op0 + nt * 8 + 2 * t) =
                make_float2(rnaf(o[mt][nt][0] * inv0), rnaf(o[mt][nt][1] * inv0));
            *(float2*)(op1 + nt * 8 + 2 * t) =
                make_float2(rnaf(o[mt][nt][2] * inv1), rnaf(o[mt][nt][3] * inv1));
        }
    }
}

// ---------------------------------------------------------------------------
// Cross-attention: 77 keys. Two-pass softmax. Output rounded (feeds out GEMM).
// ---------------------------------------------------------------------------
__global__ void __launch_bounds__(64) cross_attn_kernel()
{
    __shared__ float Kc[TL][64];
    __shared__ float Vc[TL][64];

    const int qt = blockIdx.x, h = blockIdx.y, b = blockIdx.z;
    const int tid = threadIdx.x;

    for (int i = tid; i < TL * 16; i += 64) {
        const int l = i >> 4;
        const int c4 = (i & 15);
        const size_t src = (size_t)(b * TL + l) * DM + h * 64 + c4 * 4;
        ((float4*)Kc[l])[c4] = *(const float4*)(g_kc + src);
        ((float4*)Vc[l])[c4] = *(const float4*)(g_vc + src);
    }
    __syncthreads();

    const int row = b * NSEQ + qt * 64 + tid;
    float q[64];
    {
        const float4* qp = (const float4*)(g_qb + (size_t)row * DM + h * 64);
#pragma unroll
        for (int i = 0; i < 16; i++) {
            float4 tq = qp[i];
            q[4 * i + 0] = tq.x * 0.125f;
            q[4 * i + 1] = tq.y * 0.125f;
            q[4 * i + 2] = tq.z * 0.125f;
            q[4 * i + 3] = tq.w * 0.125f;
        }
    }

    float m = -1e30f;
    for (int l = 0; l < TL; l++) {
        const float4* kr = (const float4*)Kc[l];
        float s0 = 0.f, s1 = 0.f, s2 = 0.f, s3 = 0.f;
#pragma unroll
        for (int i = 0; i < 16; i++) {
            float4 kv = kr[i];
            s0 = fmaf(q[4 * i + 0], kv.x, s0);
            s1 = fmaf(q[4 * i + 1], kv.y, s1);
            s2 = fmaf(q[4 * i + 2], kv.z, s2);
            s3 = fmaf(q[4 * i + 3], kv.w, s3);
        }
        m = fmaxf(m, (s0 + s1) + (s2 + s3));
    }

    float o[64];
#pragma unroll
    for (int d = 0; d < 64; d++) o[d] = 0.0f;
    float lsum = 0.0f;
    for (int l = 0; l < TL; l++) {
        const float4* kr = (const float4*)Kc[l];
        float s0 = 0.f, s1 = 0.f, s2 = 0.f, s3 = 0.f;
#pragma unroll
        for (int i = 0; i < 16; i++) {
            float4 kv = kr[i];
            s0 = fmaf(q[4 * i + 0], kv.x, s0);
            s1 = fmaf(q[4 * i + 1], kv.y, s1);
            s2 = fmaf(q[4 * i + 2], kv.z, s2);
            s3 = fmaf(q[4 * i + 3], kv.w, s3);
        }
        const float p = __expf((s0 + s1) + (s2 + s3) - m);
        lsum += p;
        const float4* vr = (const float4*)Vc[l];
#pragma unroll
        for (int i = 0; i < 16; i++) {
            float4 vv = vr[i];
            o[4 * i + 0] = fmaf(p, vv.x, o[4 * i + 0]);
            o[4 * i + 1] = fmaf(p, vv.y, o[4 * i + 1]);
            o[4 * i + 2] = fmaf(p, vv.z, o[4 * i + 2]);
            o[4 * i + 3] = fmaf(p, vv.w, o[4 * i + 3]);
        }
    }

    const float inv = 1.0f / lsum;
    float4* op = (float4*)(g_attn + (size_t)row * DM + h * 64);
#pragma unroll
    for (int i = 0; i < 16; i++)
        op[i] = make_float4(rnaf(o[4 * i + 0] * inv), rnaf(o[4 * i + 1] * inv),
                            rnaf(o[4 * i + 2] * inv), rnaf(o[4 * i + 3] * inv));
}

// ---------------------------------------------------------------------------
// Host side
// ---------------------------------------------------------------------------
template <int EPI, bool ROUND = false>
static void launch_gemm(const float* A, const uint32_t* W, const float* bias,
                        const float* res, float* C, int M, int N, int K)
{
    dim3 grid(N / 128, (M + 127) / 128);
    tgemm_kernel<EPI, ROUND><<<grid, 128>>>(A, W, bias, res, C, M, N, K);
}

extern "C" void kernel_launch(void* const* d_in, const int* in_sizes, int n_in,
                              void* d_out, int out_size)
{
    const float* x       = (const float*)d_in[0];
    const float* c       = (const float*)d_in[1];
    const float* text    = (const float*)d_in[2];
    const float* W_ada   = (const float*)d_in[3];
    const float* b_ada   = (const float*)d_in[4];
    const float* W_qkv   = (const float*)d_in[5];
    const float* b_qkv   = (const float*)d_in[6];
    const float* W_proj  = (const float*)d_in[7];
    const float* b_proj  = (const float*)d_in[8];
    const float* W_ctx   = (const float*)d_in[9];
    const float* b_ctx   = (const float*)d_in[10];
    const float* W_q     = (const float*)d_in[11];
    const float* W_k     = (const float*)d_in[12];
    const float* W_v     = (const float*)d_in[13];
    const float* W_out   = (const float*)d_in[14];
    const float* b_out   = (const float*)d_in[15];
    const float* W_fc1   = (const float*)d_in[16];
    const float* b_fc1   = (const float*)d_in[17];
    const float* W_fc2   = (const float*)d_in[18];
    const float* b_fc2   = (const float*)d_in[19];
    float* out = (float*)d_out;

    float *p_h, *p_qkv, *p_attn, *p_x1, *p_x2, *p_ctx, *p_qb, *p_kc, *p_vc, *p_hidden;
    uint32_t* p_wc;
    cudaGetSymbolAddress((void**)&p_h,      g_h);
    cudaGetSymbolAddress((void**)&p_qkv,    g_qkv);
    cudaGetSymbolAddress((void**)&p_attn,   g_attn);
    cudaGetSymbolAddress((void**)&p_x1,     g_x1);
    cudaGetSymbolAddress((void**)&p_x2,     g_x2);
    cudaGetSymbolAddress((void**)&p_ctx,    g_ctx);
    cudaGetSymbolAddress((void**)&p_qb,     g_qb);
    cudaGetSymbolAddress((void**)&p_kc,     g_kc);
    cudaGetSymbolAddress((void**)&p_vc,     g_vc);
    cudaGetSymbolAddress((void**)&p_hidden, g_hidden);
    cudaGetSymbolAddress((void**)&p_wc,     g_wc);

    // 0. One merged tf32 pre-convert launch (also aligns ncu skip onto a GEMM)
    {
        const uint32_t total4 = WC_TOTAL / 4;
        cvt_all_kernel<<<(total4 + 255) / 256, 256>>>(
            W_qkv, W_proj, W_ctx, W_q, W_k, W_v, W_out, W_fc1, W_fc2, text, p_wc);
    }

    // 1. adaLN modulation
    {
        dim3 grid(6 * DM / 256, BB);
        mod_kernel<<<grid, 256>>>(c, W_ada, b_ada);
    }

    // --- self-attention block ---
    lnmod_kernel<<<TTOK, 256>>>(x, 0 * DM, 1 * DM, p_h);
    launch_gemm<EPI_BIAS, true>(p_h, p_wc + OFF_QKV, b_qkv, nullptr, p_qkv, TTOK, 3 * DM, DM);
    {
        dim3 grid(NSEQ / 128, NH, BB);
        flash_attn_kernel<<<grid, 128>>>();
    }
    launch_gemm<EPI_BIAS_RES>(p_attn, p_wc + OFF_PROJ, b_proj, x, p_x1, TTOK, DM, DM);

    // --- cross-attention block ---
    lnmod_kernel<<<TTOK, 256>>>(p_x1, 2 * DM, 3 * DM, p_h);
    launch_gemm<EPI_BIAS, true>((const float*)(p_wc + OFF_TEXT), p_wc + OFF_CTX,
                                b_ctx, nullptr, p_ctx, TCTX, DM, TD);
    launch_gemm<EPI_NOBIAS>(p_h, p_wc + OFF_Q, nullptr, nullptr, p_qb, TTOK, DM, DM);
    launch_gemm<EPI_NOBIAS>(p_ctx, p_wc + OFF_K, nullptr, nullptr, p_kc, TCTX, DM, DM);
    launch_gemm<EPI_NOBIAS>(p_ctx, p_wc + OFF_V, nullptr, nullptr, p_vc, TCTX, DM, DM);
    {
        dim3 grid(NSEQ / 64, NH, BB);
        cross_attn_kernel<<<grid, 64>>>();
    }
    launch_gemm<EPI_BIAS_RES>(p_attn, p_wc + OFF_OUT, b_out, p_x1, p_x2, TTOK, DM, DM);

    // --- MLP block ---
    lnmod_kernel<<<TTOK, 256>>>(p_x2, 4 * DM, 5 * DM, p_h);
    launch_gemm<EPI_BIAS_GELU, true>(p_h, p_wc + OFF_FC1, b_fc1, nullptr, p_hidden, TTOK, 4 * DM, DM);
    launch_gemm<EPI_BIAS_RES>(p_hidden, p_wc + OFF_FC2, b_fc2, p_x2, out, TTOK, DM, 4 * DM);
}

// round 15
// speedup vs baseline: 1.1983x; 1.1983x over previous
#include <cuda_runtime.h>
#include <math.h>
#include <stdint.h>

// ---------------------------------------------------------------------------
// Problem constants
// ---------------------------------------------------------------------------
#define BB 4
#define NSEQ 1024
#define DM 1024
#define NH 16
#define HD 64
#define TD 768
#define TL 77
#define TTOK (BB * NSEQ)   // 4096
#define TCTX (BB * TL)     // 308

// ---------------------------------------------------------------------------
// Scratch (static device globals; no allocation allowed)
// ---------------------------------------------------------------------------
__device__ float g_mod[BB * 6 * DM];
__device__ float g_h[TTOK * DM];
__device__ float g_qkv[TTOK * 3 * DM];
__device__ float g_attn[TTOK * DM];
__device__ float g_x1[TTOK * DM];
__device__ float g_x2[TTOK * DM];
__device__ float g_ctx[TCTX * DM];
__device__ float g_qb[TTOK * DM];
__device__ float g_kc[TCTX * DM];
__device__ float g_vc[TCTX * DM];
__device__ float g_hidden[TTOK * 4 * DM];

// Pre-converted (tf32-rounded) weights + text, one big segment buffer.
#define OFF_QKV  0u
#define OFF_PROJ (OFF_QKV  + 1024u * 3072u)
#define OFF_CTX  (OFF_PROJ + 1024u * 1024u)
#define OFF_Q    (OFF_CTX  + 768u * 1024u)
#define OFF_K    (OFF_Q    + 1024u * 1024u)
#define OFF_V    (OFF_K    + 1024u * 1024u)
#define OFF_OUT  (OFF_V    + 1024u * 1024u)
#define OFF_FC1  (OFF_OUT  + 1024u * 1024u)
#define OFF_FC2  (OFF_FC1  + 1024u * 4096u)
#define OFF_TEXT (OFF_FC2  + 4096u * 1024u)
#define WC_TOTAL (OFF_TEXT + (uint32_t)(BB * TL * TD))
__device__ uint32_t g_wc[WC_TOTAL];

// ---------------------------------------------------------------------------
// Helpers
// ---------------------------------------------------------------------------
__device__ __forceinline__ float gelu_tanh(float x) {
    float x3 = x * x * x;
    float t  = tanhf(0.7978845608028654f * (x + 0.044715f * x3));
    return 0.5f * x * (1.0f + t);
}

__device__ __forceinline__ uint32_t f2tf32(float f) {
    uint32_t u;
    asm("cvt.rna.tf32.f32 %0, %1;" : "=r"(u) : "f"(f));
    return u;
}
__device__ __forceinline__ float rnaf(float f) {
    return __uint_as_float(f2tf32(f));
}
__device__ __forceinline__ uint4 rna4(float4 v) {
    return make_uint4(f2tf32(v.x), f2tf32(v.y), f2tf32(v.z), f2tf32(v.w));
}

__device__ __forceinline__ void mma1688(float* c, const uint32_t* a, const uint32_t* b) {
    asm volatile(
        "mma.sync.aligned.m16n8k8.row.col.f32.tf32.tf32.f32 "
        "{%0,%1,%2,%3}, {%4,%5,%6,%7}, {%8,%9}, {%0,%1,%2,%3};"
        : "+f"(c[0]), "+f"(c[1]), "+f"(c[2]), "+f"(c[3])
        : "r"(a[0]), "r"(a[1]), "r"(a[2]), "r"(a[3]), "r"(b[0]), "r"(b[1]));
}

__device__ __forceinline__ void ldsm4(uint32_t* r, uint32_t saddr) {
    asm volatile(
        "ldmatrix.sync.aligned.m8n8.x4.shared.b16 {%0,%1,%2,%3}, [%4];"
        : "=r"(r[0]), "=r"(r[1]), "=r"(r[2]), "=r"(r[3]) : "r"(saddr));
}

__device__ __forceinline__ void cpa16(uint32_t dst, const void* src, int srcBytes) {
    asm volatile("cp.async.cg.shared.global [%0], [%1], 16, %2;"
                 :: "r"(dst), "l"(src), "r"(srcBytes));
}
__device__ __forceinline__ void cpa_commit() {
    asm volatile("cp.async.commit_group;");
}
template <int N> __device__ __forceinline__ void cpa_wait() {
    asm volatile("cp.async.wait_group %0;" :: "n"(N));
}

// ---------------------------------------------------------------------------
// Single merged tf32 pre-convert kernel (all 10 segments in one launch)
// ---------------------------------------------------------------------------
__global__ void __launch_bounds__(256) cvt_all_kernel(
    const float* __restrict__ qkv, const float* __restrict__ proj,
    const float* __restrict__ ctx, const float* __restrict__ q,
    const float* __restrict__ k,   const float* __restrict__ v,
    const float* __restrict__ outw,const float* __restrict__ fc1,
    const float* __restrict__ fc2, const float* __restrict__ text,
    uint32_t* __restrict__ dst)
{
    const uint32_t i4 = blockIdx.x * 256 + threadIdx.x;
    const uint32_t total4 = WC_TOTAL / 4;
    if (i4 >= total4) return;
    const uint32_t w = i4 * 4;
    const float* src; uint32_t off;
    if      (w < OFF_PROJ) { src = qkv;  off = OFF_QKV;  }
    else if (w < OFF_CTX)  { src = proj; off = OFF_PROJ; }
    else if (w < OFF_Q)    { src = ctx;  off = OFF_CTX;  }
    else if (w < OFF_K)    { src = q;    off = OFF_Q;    }
    else if (w < OFF_V)    { src = k;    off = OFF_K;    }
    else if (w < OFF_OUT)  { src = v;    off = OFF_V;    }
    else if (w < OFF_FC1)  { src = outw; off = OFF_OUT;  }
    else if (w < OFF_FC2)  { src = fc1;  off = OFF_FC1;  }
    else if (w < OFF_TEXT) { src = fc2;  off = OFF_FC2;  }
    else                   { src = text; off = OFF_TEXT; }
    float4 vv = *(const float4*)(src + (w - off));
    *(uint4*)(dst + w) = rna4(vv);
}

// Epilogue modes
#define EPI_BIAS      0
#define EPI_BIAS_GELU 1
#define EPI_BIAS_RES  2
#define EPI_NOBIAS    3

// ---------------------------------------------------------------------------
// TF32 tensor-core GEMM v7: C[M,N] = A[M,K] @ W[K,N] (+bias)(+gelu)(+res)
// BM=BN=128, BK=16, 128 threads = 4 warps, warp tile 64x64 (measured-best
// shape from round 9) with the pipeline fixed:
//   - 3-stage cp.async ring (depth-2 prefetch, ~700+ cycles of cover)
//   - ONE __syncthreads per iteration: [wait<1> -> sync -> compute -> issue]
//     issue targets stage (it+2)%3 == (it-1)%3, whose readers are fenced by
//     this iteration's sync -> race-free. Tail commits empty groups.
// Dynamic smem: 3*(128*20 + 16*136)*4 = 56832 B (cudaFuncSetAttribute).
// Numerics identical to round 9 (same k-order, zero cvts in mainloop).
// ---------------------------------------------------------------------------
#define AS_PITCH 20
#define BS_PITCH 136
#define NSTAGE 3
#define A_STAGE_W (128 * AS_PITCH)       // words per A stage
#define B_STAGE_W (16 * BS_PITCH)        // words per B stage
#define A_STAGE_B (A_STAGE_W * 4)
#define B_STAGE_B (B_STAGE_W * 4)
#define GEMM_SMEM_B (NSTAGE * (A_STAGE_B + B_STAGE_B))   // 56832

template <int EPI, bool ROUND>
__global__ void __launch_bounds__(128) tgemm_kernel(
    const float* __restrict__ A, const uint32_t* __restrict__ W,
    const float* __restrict__ bias, const float* __restrict__ res,
    float* __restrict__ C, int M, int N, int K)
{
    extern __shared__ uint32_t smem[];
    uint32_t* BsGen = smem + NSTAGE * A_STAGE_W;

    const int tid  = threadIdx.x;
    const int lane = tid & 31;
    const int warp = tid >> 5;
    const int g = lane >> 2;
    const int t = lane & 3;
    const int wm = (warp & 1) * 64;
    const int wn = (warp >> 1) * 64;
    const int rowBase = blockIdx.y * 128;
    const int colBase = blockIdx.x * 128;

    const uint32_t asBase = (uint32_t)__cvta_generic_to_shared(smem);
    const uint32_t bsBase = (uint32_t)__cvta_generic_to_shared(BsGen);

    // ldmatrix A-fragment addresses (pitch 20 -> conflict-free)
    const int j8  = lane & 7;
    const int mtx = lane >> 3;
    uint32_t aAddr[4];
#pragma unroll
    for (int mt = 0; mt < 4; mt++)
        aAddr[mt] = asBase +
            ((wm + mt * 16 + (mtx & 1) * 8 + j8) * AS_PITCH + (mtx >> 1) * 4) * 4;

    float acc[4][8][4];
#pragma unroll
    for (int mt = 0; mt < 4; mt++)
#pragma unroll
        for (int nt = 0; nt < 8; nt++)
#pragma unroll
            for (int i = 0; i < 4; i++) acc[mt][nt][i] = 0.0f;

    // per-stage loader: A = 512 f4 (128 rows x 4 k-chunks), B = 512 f4
    auto issueStage = [&](int stage, int k0) {
#pragma unroll
        for (int i = 0; i < 4; i++) {
            const int f4 = tid + i * 128;
            const int ar = f4 >> 2, ac = (f4 & 3) * 4;
            const int row = rowBase + ar;
            const int rowC = (row < M) ? row : 0;
            cpa16(asBase + (uint32_t)stage * A_STAGE_B + (ar * AS_PITCH + ac) * 4,
                  A + (size_t)rowC * K + k0 + ac, (row < M) ? 16 : 0);
            const int bk = f4 >> 5, bn = (f4 & 31) * 4;
            cpa16(bsBase + (uint32_t)stage * B_STAGE_B + (bk * BS_PITCH + bn) * 4,
                  W + (size_t)(k0 + bk) * N + colBase + bn, 16);
        }
        cpa_commit();
    };

    const int nk = K >> 4;   // 16-k stages
    issueStage(0, 0);
    issueStage(1, 16);

    int stage = 0;
    for (int it = 0; it < nk; it++) {
        cpa_wait<1>();        // stage 'it' landed (<=1 group pending)
        __syncthreads();      // visible to all warps; readers of (it-1)%3 done

        const uint32_t aOff = (uint32_t)stage * A_STAGE_B;
        const uint32_t* __restrict__ bsBuf = BsGen + stage * B_STAGE_W;
#pragma unroll
        for (int ks = 0; ks < 16; ks += 8) {
            uint32_t af[4][4];
#pragma unroll
            for (int mt = 0; mt < 4; mt++)
                ldsm4(af[mt], aAddr[mt] + aOff + ks * 4);
            uint32_t bf[8][2];
#pragma unroll
            for (int nt = 0; nt < 8; nt++) {
                bf[nt][0] = bsBuf[(ks + t)     * BS_PITCH + wn + nt * 8 + g];
                bf[nt][1] = bsBuf[(ks + t + 4) * BS_PITCH + wn + nt * 8 + g];
            }
#pragma unroll
            for (int mt = 0; mt < 4; mt++)
#pragma unroll
                for (int nt = 0; nt < 8; nt++)
                    mma1688(acc[mt][nt], af[mt], bf[nt]);
        }

        if (it + 2 < nk) {
            // issue into stage (it+2)%3 == (it-1)%3 (safe: fenced above)
            int ns = stage + 2; if (ns >= 3) ns -= 3;
            issueStage(ns, (it + 2) * 16);
        } else {
            cpa_commit();     // empty group keeps wait<1> semantics exact
        }
        if (++stage == 3) stage = 0;
    }

    // Epilogue
#pragma unroll
    for (int mt = 0; mt < 4; mt++) {
        const int row0 = rowBase + wm + mt * 16 + g;
        const int row1 = row0 + 8;
#pragma unroll
        for (int nt = 0; nt < 8; nt++) {
            const int col = colBase + wn + nt * 8 + t * 2;
            float b0 = 0.f, b1 = 0.f;
            if (EPI != EPI_NOBIAS) { b0 = bias[col]; b1 = bias[col + 1]; }
            float v0 = acc[mt][nt][0] + b0;
            float v1 = acc[mt][nt][1] + b1;
            float v2 = acc[mt][nt][2] + b0;
            float v3 = acc[mt][nt][3] + b1;
            if (EPI == EPI_BIAS_GELU) {
                v0 = gelu_tanh(v0); v1 = gelu_tanh(v1);
                v2 = gelu_tanh(v2); v3 = gelu_tanh(v3);
            }
            if (ROUND) {
                v0 = rnaf(v0); v1 = rnaf(v1); v2 = rnaf(v2); v3 = rnaf(v3);
            }
            if (row0 < M) {
                if (EPI == EPI_BIAS_RES) {
                    float2 r = *(const float2*)(res + (size_t)row0 * N + col);
                    v0 += r.x; v1 += r.y;
                }
                *(float2*)(C + (size_t)row0 * N + col) = make_float2(v0, v1);
            }
            if (row1 < M) {
                if (EPI == EPI_BIAS_RES) {
                    float2 r = *(const float2*)(res + (size_t)row1 * N + col);
                    v2 += r.x; v3 += r.y;
                }
                *(float2*)(C + (size_t)row1 * N + col) = make_float2(v2, v3);
            }
        }
    }
}

// ---------------------------------------------------------------------------
// adaLN modulation
// ---------------------------------------------------------------------------
__global__ void __launch_bounds__(256) mod_kernel(
    const float* __restrict__ c, const float* __restrict__ W,
    const float* __restrict__ bias)
{
    const int b = blockIdx.y;
    const int col = blockIdx.x * 256 + threadIdx.x;
    __shared__ float sc[DM];
    for (int i = threadIdx.x; i < DM; i += 256) {
        float v = c[b * DM + i];
        sc[i] = v / (1.0f + __expf(-v));
    }
    __syncthreads();
    float acc = 0.0f;
#pragma unroll 8
    for (int k = 0; k < DM; k++)
        acc = fmaf(sc[k], W[(size_t)k * (6 * DM) + col], acc);
    g_mod[b * 6 * DM + col] = acc + bias[col];
}

// ---------------------------------------------------------------------------
// LayerNorm + modulate (output rounded to tf32 — feeds GEMMs only)
// ---------------------------------------------------------------------------
__global__ void __launch_bounds__(256) lnmod_kernel(
    const float* __restrict__ x, int shOff, int scOff, float* __restrict__ out)
{
    const int row = blockIdx.x;
    const int b = row >> 10;
    const int tid = threadIdx.x;

    float4 v = ((const float4*)(x + (size_t)row * DM))[tid];
    float s  = v.x + v.y + v.z + v.w;
    float s2 = v.x * v.x + v.y * v.y + v.z * v.z + v.w * v.w;

    __shared__ float red[16];
#pragma unroll
    for (int off = 16; off > 0; off >>= 1) {
        s  += __shfl_xor_sync(0xffffffffu, s,  off);
        s2 += __shfl_xor_sync(0xffffffffu, s2, off);
    }
    const int warp = tid >> 5, lane = tid & 31;
    if (lane == 0) { red[warp] = s; red[warp + 8] = s2; }
    __syncthreads();
    if (tid == 0) {
        float ts = 0.f, ts2 = 0.f;
#pragma unroll
        for (int i = 0; i < 8; i++) { ts += red[i]; ts2 += red[i + 8]; }
        float mu  = ts * (1.0f / DM);
        float var = ts2 * (1.0f / DM) - mu * mu;
        red[0] = mu;
        red[1] = rsqrtf(var + 1e-6f);
    }
    __syncthreads();
    const float mu = red[0], rs = red[1];

    const float* modp = g_mod + b * 6 * DM;
    const int cc = tid * 4;
    float4 sh  = *(const float4*)(modp + shOff + cc);
    float4 scv = *(const float4*)(modp + scOff + cc);
    float4 o;
    o.x = rnaf((v.x - mu) * rs * (1.0f + scv.x) + sh.x);
    o.y = rnaf((v.y - mu) * rs * (1.0f + scv.y) + sh.y);
    o.z = rnaf((v.z - mu) * rs * (1.0f + scv.z) + sh.z);
    o.w = rnaf((v.w - mu) * rs * (1.0f + scv.w) + sh.w);
    ((float4*)(out + (size_t)row * DM))[tid] = o;
}

// ---------------------------------------------------------------------------
// Tensor-core flash self-attention v3 (unchanged — 167us measured).
// ---------------------------------------------------------------------------
#define KS_PITCH 76
#define VS_PITCH 88

__global__ void __launch_bounds__(128) flash_attn_kernel()
{
    __shared__ uint32_t Ks[64][KS_PITCH];
    __shared__ uint32_t Vs[64][VS_PITCH];

    const int qt = blockIdx.x, h = blockIdx.y, b = blockIdx.z;
    const int tid  = threadIdx.x;
    const int lane = tid & 31;
    const int warp = tid >> 5;
    const int g = lane >> 2;
    const int t = lane & 3;
    const int rw = warp * 32;
    const int qbase = b * NSEQ + qt * 128;

    uint32_t qa[8][2][4];
#pragma unroll
    for (int mt = 0; mt < 2; mt++) {
        const float* q0 = g_qkv + (size_t)(qbase + rw + mt * 16 + g) * (3 * DM) + h * 64;
        const float* q1 = q0 + (size_t)8 * (3 * DM);
#pragma unroll
        for (int ks = 0; ks < 8; ks++) {
            qa[ks][mt][0] = __float_as_uint(q0[ks * 8 + t]     * 0.125f);
            qa[ks][mt][1] = __float_as_uint(q1[ks * 8 + t]     * 0.125f);
            qa[ks][mt][2] = __float_as_uint(q0[ks * 8 + t + 4] * 0.125f);
            qa[ks][mt][3] = __float_as_uint(q1[ks * 8 + t + 4] * 0.125f);
        }
    }

    float o[2][8][4];
#pragma unroll
    for (int mt = 0; mt < 2; mt++)
#pragma unroll
        for (int nt = 0; nt < 8; nt++)
#pragma unroll
            for (int i = 0; i < 4; i++) o[mt][nt][i] = 0.0f;
    float mrow[2][2] = {{-1e30f, -1e30f}, {-1e30f, -1e30f}};
    float lrow[2][2] = {{0.f, 0.f}, {0.f, 0.f}};

    const int j8  = lane & 7;
    const int mtx = lane >> 3;
    const uint32_t ksBase = (uint32_t)__cvta_generic_to_shared(&Ks[0][0]);
    uint32_t kAddr[2];
#pragma unroll
    for (int p = 0; p < 2; p++)
        kAddr[p] = ksBase +
            ((p * 16 + (mtx >> 1) * 8 + j8) * KS_PITCH + (mtx & 1) * 4) * 4;

    const int src0 = (lane & ~3) | (t >> 1);
    const int src2 = src0 + 2;
    const bool odd = (t & 1) != 0;

    for (int kt = 0; kt < 16; kt++) {
        __syncthreads();
#pragma unroll
        for (int i = 0; i < 8; i++) {
            const int f4 = tid + i * 128;
            const int rk = f4 >> 4, c4 = f4 & 15;
            const size_t krow = (size_t)(b * NSEQ + kt * 64 + rk) * (3 * DM);
            *(uint4*)&Ks[rk][c4 * 4] =
                *(const uint4*)(g_qkv + krow + DM     + h * 64 + c4 * 4);
            *(uint4*)&Vs[rk][c4 * 4] =
                *(const uint4*)(g_qkv + krow + 2 * DM + h * 64 + c4 * 4);
        }
        __syncthreads();

#pragma unroll
        for (int c = 0; c < 2; c++) {
            float s[2][4][4];
#pragma unroll
            for (int mt = 0; mt < 2; mt++)
#pragma unroll
                for (int nt = 0; nt < 4; nt++)
#pragma unroll
                    for (int i = 0; i < 4; i++) s[mt][nt][i] = 0.0f;

#pragma unroll
            for (int ks = 0; ks < 8; ks++) {
                uint32_t bq[2][4];
#pragma unroll
                for (int p = 0; p < 2; p++)
                    ldsm4(bq[p], kAddr[p] + c * (32 * KS_PITCH * 4) + ks * 32);
#pragma unroll
                for (int mt = 0; mt < 2; mt++) {
                    mma1688(s[mt][0], qa[ks][mt], &bq[0][0]);
                    mma1688(s[mt][1], qa[ks][mt], &bq[0][2]);
                    mma1688(s[mt][2], qa[ks][mt], &bq[1][0]);
                    mma1688(s[mt][3], qa[ks][mt], &bq[1][2]);
                }
            }

#pragma unroll
            for (int mt = 0; mt < 2; mt++) {
                float tmax0 = -1e30f, tmax1 = -1e30f;
#pragma unroll
                for (int nt = 0; nt < 4; nt++) {
                    tmax0 = fmaxf(tmax0, fmaxf(s[mt][nt][0], s[mt][nt][1]));
                    tmax1 = fmaxf(tmax1, fmaxf(s[mt][nt][2], s[mt][nt][3]));
                }
                tmax0 = fmaxf(tmax0, __shfl_xor_sync(0xffffffffu, tmax0, 1));
                tmax0 = fmaxf(tmax0, __shfl_xor_sync(0xffffffffu, tmax0, 2));
                tmax1 = fmaxf(tmax1, __shfl_xor_sync(0xffffffffu, tmax1, 1));
                tmax1 = fmaxf(tmax1, __shfl_xor_sync(0xffffffffu, tmax1, 2));

                const float mn0 = fmaxf(mrow[mt][0], tmax0);
                const float mn1 = fmaxf(mrow[mt][1], tmax1);
                const float corr0 = __expf(mrow[mt][0] - mn0);
                const float corr1 = __expf(mrow[mt][1] - mn1);

                float sum0 = 0.f, sum1 = 0.f;
#pragma unroll
                for (int nt = 0; nt < 4; nt++) {
                    s[mt][nt][0] = __expf(s[mt][nt][0] - mn0); sum0 += s[mt][nt][0];
                    s[mt][nt][1] = __expf(s[mt][nt][1] - mn0); sum0 += s[mt][nt][1];
                    s[mt][nt][2] = __expf(s[mt][nt][2] - mn1); sum1 += s[mt][nt][2];
                    s[mt][nt][3] = __expf(s[mt][nt][3] - mn1); sum1 += s[mt][nt][3];
                }
                sum0 += __shfl_xor_sync(0xffffffffu, sum0, 1);
                sum0 += __shfl_xor_sync(0xffffffffu, sum0, 2);
                sum1 += __shfl_xor_sync(0xffffffffu, sum1, 1);
                sum1 += __shfl_xor_sync(0xffffffffu, sum1, 2);

                lrow[mt][0] = lrow[mt][0] * corr0 + sum0;
                lrow[mt][1] = lrow[mt][1] * corr1 + sum1;
                mrow[mt][0] = mn0; mrow[mt][1] = mn1;
#pragma unroll
                for (int nt = 0; nt < 8; nt++) {
                    o[mt][nt][0] *= corr0; o[mt][nt][1] *= corr0;
                    o[mt][nt][2] *= corr1; o[mt][nt][3] *= corr1;
                }
            }

#pragma unroll
            for (int kv_ = 0; kv_ < 4; kv_++) {
                const int kk = c * 32 + kv_ * 8;
                uint32_t pa[2][4];
#pragma unroll
                for (int mt = 0; mt < 2; mt++) {
                    float v0 = __shfl_sync(0xffffffffu, s[mt][kv_][0], src0);
                    float v1 = __shfl_sync(0xffffffffu, s[mt][kv_][1], src0);
                    float v2 = __shfl_sync(0xffffffffu, s[mt][kv_][2], src0);
                    float v3 = __shfl_sync(0xffffffffu, s[mt][kv_][3], src0);
                    float w0 = __shfl_sync(0xffffffffu, s[mt][kv_][0], src2);
                    float w1 = __shfl_sync(0xffffffffu, s[mt][kv_][1], src2);
                    float w2 = __shfl_sync(0xffffffffu, s[mt][kv_][2], src2);
                    float w3 = __shfl_sync(0xffffffffu, s[mt][kv_][3], src2);
                    pa[mt][0] = __float_as_uint(odd ? v1 : v0);
                    pa[mt][1] = __float_as_uint(odd ? v3 : v2);
                    pa[mt][2] = __float_as_uint(odd ? w1 : w0);
                    pa[mt][3] = __float_as_uint(odd ? w3 : w2);
                }
#pragma unroll
                for (int nt = 0; nt < 8; nt++) {
                    uint32_t bv[2];
                    bv[0] = Vs[kk + t][nt * 8 + g];
                    bv[1] = Vs[kk + t + 4][nt * 8 + g];
                    mma1688(o[0][nt], pa[0], bv);
                    mma1688(o[1][nt], pa[1], bv);
                }
            }
        }
    }

#pragma unroll
    for (int mt = 0; mt < 2; mt++) {
        const float inv0 = 1.0f / lrow[mt][0];
        const float inv1 = 1.0f / lrow[mt][1];
        float* op0 = g_attn + (size_t)(qbase + rw + mt * 16 + g) * DM + h * 64;
        float* op1 = op0 + (size_t)8 * DM;
#pragma unroll
        for (int nt = 0; nt < 8; nt++) {
            *(float2*)(op0 + nt * 8 + 2 * t) =
                make_float2(rnaf(o[mt][nt][0] * inv0), rnaf(o[mt][nt][1] * inv0));
            *(float2*)(op1 + nt * 8 + 2 * t) =
                make_float2(rnaf(o[mt][nt][2] * inv1), rnaf(o[mt][nt][3] * inv1));
        }
    }
}

// ---------------------------------------------------------------------------
// Cross-attention: 77 keys. Two-pass softmax. Output rounded (feeds out GEMM).
// ---------------------------------------------------------------------------
__global__ void __launch_bounds__(64) cross_attn_kernel()
{
    __shared__ float Kc[TL][64];
    __shared__ float Vc[TL][64];

    const int qt = blockIdx.x, h = blockIdx.y, b = blockIdx.z;
    const int tid = threadIdx.x;

    for (int i = tid; i < TL * 16; i += 64) {
        const int l = i >> 4;
        const int c4 = (i & 15);
        const size_t src = (size_t)(b * TL + l) * DM + h * 64 + c4 * 4;
        ((float4*)Kc[l])[c4] = *(const float4*)(g_kc + src);
        ((float4*)Vc[l])[c4] = *(const float4*)(g_vc + src);
    }
    __syncthreads();

    const int row = b * NSEQ + qt * 64 + tid;
    float q[64];
    {
        const float4* qp = (const float4*)(g_qb + (size_t)row * DM + h * 64);
#pragma unroll
        for (int i = 0; i < 16; i++) {
            float4 tq = qp[i];
            q[4 * i + 0] = tq.x * 0.125f;
            q[4 * i + 1] = tq.y * 0.125f;
            q[4 * i + 2] = tq.z * 0.125f;
            q[4 * i + 3] = tq.w * 0.125f;
        }
    }

    float m = -1e30f;
    for (int l = 0; l < TL; l++) {
        const float4* kr = (const float4*)Kc[l];
        float s0 = 0.f, s1 = 0.f, s2 = 0.f, s3 = 0.f;
#pragma unroll
        for (int i = 0; i < 16; i++) {
            float4 kv = kr[i];
            s0 = fmaf(q[4 * i + 0], kv.x, s0);
            s1 = fmaf(q[4 * i + 1], kv.y, s1);
            s2 = fmaf(q[4 * i + 2], kv.z, s2);
            s3 = fmaf(q[4 * i + 3], kv.w, s3);
        }
        m = fmaxf(m, (s0 + s1) + (s2 + s3));
    }

    float o[64];
#pragma unroll
    for (int d = 0; d < 64; d++) o[d] = 0.0f;
    float lsum = 0.0f;
    for (int l = 0; l < TL; l++) {
        const float4* kr = (const float4*)Kc[l];
        float s0 = 0.f, s1 = 0.f, s2 = 0.f, s3 = 0.f;
#pragma unroll
        for (int i = 0; i < 16; i++) {
            float4 kv = kr[i];
            s0 = fmaf(q[4 * i + 0], kv.x, s0);
            s1 = fmaf(q[4 * i + 1], kv.y, s1);
            s2 = fmaf(q[4 * i + 2], kv.z, s2);
            s3 = fmaf(q[4 * i + 3], kv.w, s3);
        }
        const float p = __expf((s0 + s1) + (s2 + s3) - m);
        lsum += p;
        const float4* vr = (const float4*)Vc[l];
#pragma unroll
        for (int i = 0; i < 16; i++) {
            float4 vv = vr[i];
            o[4 * i + 0] = fmaf(p, vv.x, o[4 * i + 0]);
            o[4 * i + 1] = fmaf(p, vv.y, o[4 * i + 1]);
            o[4 * i + 2] = fmaf(p, vv.z, o[4 * i + 2]);
            o[4 * i + 3] = fmaf(p, vv.w, o[4 * i + 3]);
        }
    }

    const float inv = 1.0f / lsum;
    float4* op = (float4*)(g_attn + (size_t)row * DM + h * 64);
#pragma unroll
    for (int i = 0; i < 16; i++)
        op[i] = make_float4(rnaf(o[4 * i + 0] * inv), rnaf(o[4 * i + 1] * inv),
                            rnaf(o[4 * i + 2] * inv), rnaf(o[4 * i + 3] * inv));
}

// ---------------------------------------------------------------------------
// Host side
// ---------------------------------------------------------------------------
template <int EPI, bool ROUND = false>
static void launch_gemm(const float* A, const uint32_t* W, const float* bias,
                        const float* res, float* C, int M, int N, int K)
{
    static bool attrSet = false;
    if (!attrSet) {
        cudaFuncSetAttribute(tgemm_kernel<EPI, ROUND>,
                             cudaFuncAttributeMaxDynamicSharedMemorySize,
                             GEMM_SMEM_B);
        attrSet = true;
    }
    dim3 grid(N / 128, (M + 127) / 128);
    tgemm_kernel<EPI, ROUND><<<grid, 128, GEMM_SMEM_B>>>(A, W, bias, res, C, M, N, K);
}

extern "C" void kernel_launch(void* const* d_in, const int* in_sizes, int n_in,
                              void* d_out, int out_size)
{
    const float* x       = (const float*)d_in[0];
    const float* c       = (const float*)d_in[1];
    const float* text    = (const float*)d_in[2];
    const float* W_ada   = (const float*)d_in[3];
    const float* b_ada   = (const float*)d_in[4];
    const float* W_qkv   = (const float*)d_in[5];
    const float* b_qkv   = (const float*)d_in[6];
    const float* W_proj  = (const float*)d_in[7];
    const float* b_proj  = (const float*)d_in[8];
    const float* W_ctx   = (const float*)d_in[9];
    const float* b_ctx   = (const float*)d_in[10];
    const float* W_q     = (const float*)d_in[11];
    const float* W_k     = (const float*)d_in[12];
    const float* W_v     = (const float*)d_in[13];
    const float* W_out   = (const float*)d_in[14];
    const float* b_out   = (const float*)d_in[15];
    const float* W_fc1   = (const float*)d_in[16];
    const float* b_fc1   = (const float*)d_in[17];
    const float* W_fc2   = (const float*)d_in[18];
    const float* b_fc2   = (const float*)d_in[19];
    float* out = (float*)d_out;

    float *p_h, *p_qkv, *p_attn, *p_x1, *p_x2, *p_ctx, *p_qb, *p_kc, *p_vc, *p_hidden;
    uint32_t* p_wc;
    cudaGetSymbolAddress((void**)&p_h,      g_h);
    cudaGetSymbolAddress((void**)&p_qkv,    g_qkv);
    cudaGetSymbolAddress((void**)&p_attn,   g_attn);
    cudaGetSymbolAddress((void**)&p_x1,     g_x1);
    cudaGetSymbolAddress((void**)&p_x2,     g_x2);
    cudaGetSymbolAddress((void**)&p_ctx,    g_ctx);
    cudaGetSymbolAddress((void**)&p_qb,     g_qb);
    cudaGetSymbolAddress((void**)&p_kc,     g_kc);
    cudaGetSymbolAddress((void**)&p_vc,     g_vc);
    cudaGetSymbolAddress((void**)&p_hidden, g_hidden);
    cudaGetSymbolAddress((void**)&p_wc,     g_wc);

    // 0. One merged tf32 pre-convert launch
    {
        const uint32_t total4 = WC_TOTAL / 4;
        cvt_all_kernel<<<(total4 + 255) / 256, 256>>>(
            W_qkv, W_proj, W_ctx, W_q, W_k, W_v, W_out, W_fc1, W_fc2, text, p_wc);
    }

    // 1. adaLN modulation
    {
        dim3 grid(6 * DM / 256, BB);
        mod_kernel<<<grid, 256>>>(c, W_ada, b_ada);
    }

    // --- self-attention block ---
    lnmod_kernel<<<TTOK, 256>>>(x, 0 * DM, 1 * DM, p_h);
    launch_gemm<EPI_BIAS, true>(p_h, p_wc + OFF_QKV, b_qkv, nullptr, p_qkv, TTOK, 3 * DM, DM);
    {
        dim3 grid(NSEQ / 128, NH, BB);
        flash_attn_kernel<<<grid, 128>>>();
    }
    launch_gemm<EPI_BIAS_RES>(p_attn, p_wc + OFF_PROJ, b_proj, x, p_x1, TTOK, DM, DM);

    // --- cross-attention block ---
    lnmod_kernel<<<TTOK, 256>>>(p_x1, 2 * DM, 3 * DM, p_h);
    launch_gemm<EPI_BIAS, true>((const float*)(p_wc + OFF_TEXT), p_wc + OFF_CTX,
                                b_ctx, nullptr, p_ctx, TCTX, DM, TD);
    launch_gemm<EPI_NOBIAS>(p_h, p_wc + OFF_Q, nullptr, nullptr, p_qb, TTOK, DM, DM);
    launch_gemm<EPI_NOBIAS>(p_ctx, p_wc + OFF_K, nullptr, nullptr, p_kc, TCTX, DM, DM);
    launch_gemm<EPI_NOBIAS>(p_ctx, p_wc + OFF_V, nullptr, nullptr, p_vc, TCTX, DM, DM);
    {
        dim3 grid(NSEQ / 64, NH, BB);
        cross_attn_kernel<<<grid, 64>>>();
    }
    launch_gemm<EPI_BIAS_RES>(p_attn, p_wc + OFF_OUT, b_out, p_x1, p_x2, TTOK, DM, DM);

    // --- MLP block ---
    lnmod_kernel<<<TTOK, 256>>>(p_x2, 4 * DM, 5 * DM, p_h);
    launch_gemm<EPI_BIAS_GELU, true>(p_h, p_wc + OFF_FC1, b_fc1, nullptr, p_hidden, TTOK, 4 * DM, DM);
    launch_gemm<EPI_BIAS_RES>(p_hidden, p_wc + OFF_FC2, b_fc2, p_x2, out, TTOK, DM, 4 * DM);
}